// round 17
// baseline (speedup 1.0000x reference)
#include <cuda_runtime.h>
#include <cuda_bf16.h>
#include <cuda_fp16.h>

#define B_ 8
#define C_ 192
#define N_ 16384
#define NH_ 6
#define HD_ 32

// Scratch (device globals: allocation-free per harness rules)
__device__ __nv_bfloat16 g_q[B_*C_*N_];
__device__ __nv_bfloat16 g_k[B_*C_*N_];
__device__ __half g_v[B_*C_*N_];
__device__ float g_ssq[2*B_*C_];   // two half-plane partials
__device__ float g_ssk[2*B_*C_];
__device__ float g_G[B_*NH_*HD_*HD_];
__device__ float g_M[B_*C_*C_];

__device__ __forceinline__ unsigned su32(const void* p) {
    unsigned r;
    asm("{ .reg .u64 t; cvta.to.shared.u64 t, %1; cvt.u32.u64 %0, t; }"
        : "=r"(r) : "l"(p));
    return r;
}
// pack (lo=a, hi=b) into one bf16x2 word
__device__ __forceinline__ unsigned bf2(float lo, float hi) {
    unsigned r;
    asm("cvt.rn.bf16x2.f32 %0, %1, %2;" : "=r"(r) : "f"(hi), "f"(lo));
    return r;
}
// packed f32x2 helpers (sm_103a)
__device__ __forceinline__ unsigned long long pack2(float lo, float hi) {
    unsigned long long r;
    asm("mov.b64 %0, {%1, %2};" : "=l"(r) : "f"(lo), "f"(hi));
    return r;
}
__device__ __forceinline__ void fma2(unsigned long long& d, unsigned long long a,
                                     unsigned long long b, unsigned long long c) {
    asm("fma.rn.f32x2 %0, %1, %2, %3;" : "=l"(d) : "l"(a), "l"(b), "l"(c));
}
__device__ __forceinline__ float2 unpack2(unsigned long long v) {
    float2 f;
    asm("mov.b64 {%0, %1}, %2;" : "=f"(f.x), "=f"(f.y) : "l"(v));
    return f;
}
#define CP_ASYNC16(s, g) asm volatile("cp.async.ca.shared.global [%0], [%1], 16;" :: "r"(s), "l"(g))
#define CP_COMMIT()      asm volatile("cp.async.commit_group;")
#define CP_WAIT(n)       asm volatile("cp.async.wait_group %0;" :: "n"(n))

__device__ __forceinline__ void ldsm_x4(unsigned& r0, unsigned& r1, unsigned& r2,
                                        unsigned& r3, unsigned addr) {
    asm volatile("ldmatrix.sync.aligned.m8n8.x4.shared.b16 {%0,%1,%2,%3}, [%4];"
                 : "=r"(r0), "=r"(r1), "=r"(r2), "=r"(r3) : "r"(addr));
}
__device__ __forceinline__ void ldsm_x2(unsigned& r0, unsigned& r1, unsigned addr) {
    asm volatile("ldmatrix.sync.aligned.m8n8.x2.shared.b16 {%0,%1}, [%2];"
                 : "=r"(r0), "=r"(r1) : "r"(addr));
}
__device__ __forceinline__ void ldsm_x4_t(unsigned& r0, unsigned& r1, unsigned& r2,
                                          unsigned& r3, unsigned addr) {
    asm volatile("ldmatrix.sync.aligned.m8n8.x4.trans.shared.b16 {%0,%1,%2,%3}, [%4];"
                 : "=r"(r0), "=r"(r1), "=r"(r2), "=r"(r3) : "r"(addr));
}
__device__ __forceinline__ void mma_bf16(float& c0, float& c1, float& c2, float& c3,
                                         unsigned a0, unsigned a1, unsigned a2, unsigned a3,
                                         unsigned b0, unsigned b1) {
    asm volatile(
        "mma.sync.aligned.m16n8k16.row.col.f32.bf16.bf16.f32 "
        "{%0,%1,%2,%3}, {%4,%5,%6,%7}, {%8,%9}, {%0,%1,%2,%3};"
        : "+f"(c0), "+f"(c1), "+f"(c2), "+f"(c3)
        : "r"(a0), "r"(a1), "r"(a2), "r"(a3), "r"(b0), "r"(b1));
}
__device__ __forceinline__ void mma_fp16(float& c0, float& c1, float& c2, float& c3,
                                         unsigned a0, unsigned a1, unsigned a2, unsigned a3,
                                         unsigned b0, unsigned b1) {
    asm volatile(
        "mma.sync.aligned.m16n8k16.row.col.f32.f16.f16.f32 "
        "{%0,%1,%2,%3}, {%4,%5,%6,%7}, {%8,%9}, {%0,%1,%2,%3};"
        : "+f"(c0), "+f"(c1), "+f"(c2), "+f"(c3)
        : "r"(a0), "r"(a1), "r"(a2), "r"(a3), "r"(b0), "r"(b1));
}

// ---------------------------------------------------------------------------
// K0: no-op shims (profiling alignment: ncu captures the 4th launch).
// ---------------------------------------------------------------------------
__global__ void nop_k() {}

// ---------------------------------------------------------------------------
// K1: depthwise 3x3 conv, half-plane blocks, packed f32x2 compute:
// pixel pairs share tap packs; 9 FFMA2 per pair per channel (vs 18 FFMA).
// q/k -> bf16 (+ssq/ssk partials); v -> fp16.
// ---------------------------------------------------------------------------
__global__ __launch_bounds__(256) void conv_k(const float* __restrict__ x,
                                              const float* __restrict__ w,
                                              const float* __restrict__ bias) {
    const int RS = 132;
    extern __shared__ float tile[];    // [66][132]
    int cin = blockIdx.x, half = blockIdx.y, b = blockIdx.z;
    int tid = threadIdx.x, wid = tid >> 5, lane = tid & 31;
    if (b == 0 && half == 0 && cin < 48) {
        float* Gz = g_G + cin * 1024;
        for (int i = tid; i < 1024; i += 256) Gz[i] = 0.f;
    }
    int r0 = half * 64;
    const float* xp = x + ((size_t)b * C_ + cin) * N_;
    for (int rr = wid; rr < 66; rr += 8) {
        int yy = r0 + rr - 1;
        bool rowok = (unsigned)yy < 128u;
        const float* rp = xp + yy * 128 - 1;
        float* tp = tile + rr * RS;
#pragma unroll
        for (int c = lane; c < 130; c += 32) {
            float v = 0.f;
            if (rowok && c >= 1 && c <= 128) v = rp[c];
            tp[c] = v;
        }
    }
    __syncthreads();

    int o0 = cin * 3;
    // packed weights / bias
    unsigned long long wp[3][9], bp[3];
#pragma unroll
    for (int j = 0; j < 3; j++) {
        int o = o0 + j;
        float bb = bias[o];
        bp[j] = pack2(bb, bb);
#pragma unroll
        for (int t = 0; t < 9; t++) {
            float wv = w[o * 9 + t];
            wp[j][t] = pack2(wv, wv);
        }
    }
    size_t hoff = (size_t)r0 * 128;

    if (cin < 128) {
        __nv_bfloat16* dst[3];
#pragma unroll
        for (int j = 0; j < 3; j++) {
            int o = o0 + j;
            if (o < C_) dst[j] = g_q + ((size_t)b * C_ + o) * N_ + hoff;
            else        dst[j] = g_k + ((size_t)b * C_ + (o - C_)) * N_ + hoff;
        }
        unsigned long long ssp[3] = {0ull, 0ull, 0ull};
#pragma unroll
        for (int q = 0; q < 8; q++) {
            int p4 = tid + q * 256;
            int r = p4 >> 5, cc = (p4 & 31) << 2;
            const float* trow = tile + r * RS + cc;
            unsigned long long P[3][5];
#pragma unroll
            for (int dy = 0; dy < 3; dy++) {
                float4 f = *(const float4*)(trow + dy * RS);
                float2 g2 = *(const float2*)(trow + dy * RS + 4);
                P[dy][0] = pack2(f.x, f.y);
                P[dy][1] = pack2(f.y, f.z);
                P[dy][2] = pack2(f.z, f.w);
                P[dy][3] = pack2(f.w, g2.x);
                P[dy][4] = pack2(g2.x, g2.y);
            }
#pragma unroll
            for (int j = 0; j < 3; j++) {
                unsigned long long a0 = bp[j], a1 = bp[j];
#pragma unroll
                for (int dy = 0; dy < 3; dy++) {
                    fma2(a0, wp[j][dy * 3 + 0], P[dy][0], a0);
                    fma2(a0, wp[j][dy * 3 + 1], P[dy][1], a0);
                    fma2(a0, wp[j][dy * 3 + 2], P[dy][2], a0);
                    fma2(a1, wp[j][dy * 3 + 0], P[dy][2], a1);
                    fma2(a1, wp[j][dy * 3 + 1], P[dy][3], a1);
                    fma2(a1, wp[j][dy * 3 + 2], P[dy][4], a1);
                }
                fma2(ssp[j], a0, a0, ssp[j]);
                fma2(ssp[j], a1, a1, ssp[j]);
                float2 f0 = unpack2(a0), f1 = unpack2(a1);
                uint2 pk = make_uint2(bf2(f0.x, f0.y), bf2(f1.x, f1.y));
                *(uint2*)(dst[j] + p4 * 4) = pk;
            }
        }
        __shared__ float red[3][8];
#pragma unroll
        for (int j = 0; j < 3; j++) {
            float2 sf = unpack2(ssp[j]);
            float v = sf.x + sf.y;
#pragma unroll
            for (int off = 16; off > 0; off >>= 1) v += __shfl_xor_sync(0xffffffffu, v, off);
            if (lane == 0) red[j][wid] = v;
        }
        __syncthreads();
        if (tid < 3) {
            float t = 0.f;
#pragma unroll
            for (int wd = 0; wd < 8; wd++) t += red[tid][wd];
            int o = o0 + tid;
            int part = half * B_ * C_;
            if (o < C_) g_ssq[part + b * C_ + o] = t;
            else        g_ssk[part + b * C_ + (o - C_)] = t;
        }
    } else {
        __half* dst[3];
#pragma unroll
        for (int j = 0; j < 3; j++)
            dst[j] = g_v + ((size_t)b * C_ + (o0 + j - 2 * C_)) * N_ + hoff;
#pragma unroll
        for (int q = 0; q < 8; q++) {
            int p4 = tid + q * 256;
            int r = p4 >> 5, cc = (p4 & 31) << 2;
            const float* trow = tile + r * RS + cc;
            unsigned long long P[3][5];
#pragma unroll
            for (int dy = 0; dy < 3; dy++) {
                float4 f = *(const float4*)(trow + dy * RS);
                float2 g2 = *(const float2*)(trow + dy * RS + 4);
                P[dy][0] = pack2(f.x, f.y);
                P[dy][1] = pack2(f.y, f.z);
                P[dy][2] = pack2(f.z, f.w);
                P[dy][3] = pack2(f.w, g2.x);
                P[dy][4] = pack2(g2.x, g2.y);
            }
#pragma unroll
            for (int j = 0; j < 3; j++) {
                unsigned long long a0 = bp[j], a1 = bp[j];
#pragma unroll
                for (int dy = 0; dy < 3; dy++) {
                    fma2(a0, wp[j][dy * 3 + 0], P[dy][0], a0);
                    fma2(a0, wp[j][dy * 3 + 1], P[dy][1], a0);
                    fma2(a0, wp[j][dy * 3 + 2], P[dy][2], a0);
                    fma2(a1, wp[j][dy * 3 + 0], P[dy][2], a1);
                    fma2(a1, wp[j][dy * 3 + 1], P[dy][3], a1);
                    fma2(a1, wp[j][dy * 3 + 2], P[dy][4], a1);
                }
                float2 f0 = unpack2(a0), f1 = unpack2(a1);
                __half2 h01 = __floats2half2_rn(f0.x, f0.y);
                __half2 h23 = __floats2half2_rn(f1.x, f1.y);
                uint2 pk = make_uint2(*(unsigned*)&h01, *(unsigned*)&h23);
                *(uint2*)(dst[j] + p4 * 4) = pk;
            }
        }
    }
}

// ---------------------------------------------------------------------------
// K2: gram G[b,h] += q_h @ k_h^T via mma.sync bf16 (m16n8k16) + ldmatrix.
// ---------------------------------------------------------------------------
#define GROW 272
#define GARR (32 * GROW)
#define GBUF (2 * GARR)
#define GRAM_SMEM (2 * GBUF)

__global__ __launch_bounds__(128) void gram_k() {
    extern __shared__ char gsm[];
    unsigned smem_base = su32(gsm);
    int chunk = blockIdx.x, h = blockIdx.y, b = blockIdx.z;
    const __nv_bfloat16* qb = g_q + ((size_t)b * C_ + h * HD_) * N_;
    const __nv_bfloat16* kb = g_k + ((size_t)b * C_ + h * HD_) * N_;
    int tid = threadIdx.x, wid = tid >> 5, lane = tid & 31;
    int n0 = chunk * 1024;

    int mt = wid & 1;
    int nb0 = (wid >> 1) * 2;

    auto stage = [&](int sub, int buf) {
        unsigned dstq = smem_base + buf * GBUF;
        unsigned dstk = dstq + GARR;
        int r = tid >> 4, s16 = tid & 15;
#pragma unroll
        for (int i = 0; i < 4; i++) {
            int row = r + i * 8;
            const __nv_bfloat16* sq = qb + (size_t)row * N_ + n0 + sub * 128 + s16 * 8;
            const __nv_bfloat16* sk = kb + (size_t)row * N_ + n0 + sub * 128 + s16 * 8;
            CP_ASYNC16(dstq + row * GROW + s16 * 16, sq);
            CP_ASYNC16(dstk + row * GROW + s16 * 16, sk);
        }
        CP_COMMIT();
    };

    stage(0, 0);

    float acc[2][4];
#pragma unroll
    for (int nbi = 0; nbi < 2; nbi++)
#pragma unroll
        for (int p = 0; p < 4; p++) acc[nbi][p] = 0.f;

    unsigned a_off = (lane & 15) * GROW + (lane >> 4) * 16;
    unsigned b_off = (lane & 7) * GROW + ((lane >> 3) & 1) * 16;

    for (int sub = 0; sub < 8; sub++) {
        int buf = sub & 1;
        if (sub < 7) { stage(sub + 1, buf ^ 1); CP_WAIT(1); }
        else         { CP_WAIT(0); }
        __syncthreads();
        unsigned qs = smem_base + buf * GBUF + mt * 16 * GROW;
        unsigned ks = smem_base + buf * GBUF + GARR;
#pragma unroll
        for (int ksix = 0; ksix < 8; ksix++) {
            unsigned a0, a1, a2, a3;
            ldsm_x4(a0, a1, a2, a3, qs + a_off + ksix * 32);
#pragma unroll
            for (int nbi = 0; nbi < 2; nbi++) {
                unsigned b0, b1;
                ldsm_x2(b0, b1, ks + (nb0 + nbi) * 8 * GROW + b_off + ksix * 32);
                mma_bf16(acc[nbi][0], acc[nbi][1], acc[nbi][2], acc[nbi][3],
                         a0, a1, a2, a3, b0, b1);
            }
        }
        __syncthreads();
    }

    float* Gp = g_G + ((b * NH_ + h) << 10);
    int row = lane >> 2, colp = 2 * (lane & 3);
#pragma unroll
    for (int nbi = 0; nbi < 2; nbi++) {
        int cbase = (nb0 + nbi) * 8 + colp;
        atomicAdd(&Gp[(mt * 16 + row) * 32 + cbase],         acc[nbi][0]);
        atomicAdd(&Gp[(mt * 16 + row) * 32 + cbase + 1],     acc[nbi][1]);
        atomicAdd(&Gp[(mt * 16 + row + 8) * 32 + cbase],     acc[nbi][2]);
        atomicAdd(&Gp[(mt * 16 + row + 8) * 32 + cbase + 1], acc[nbi][3]);
    }
}

// ---------------------------------------------------------------------------
// K3: softmax + compose M[b] = w_out @ blockdiag(attn heads). grid (6, B).
// ---------------------------------------------------------------------------
__global__ __launch_bounds__(256) void compose_k(const float* __restrict__ temp,
                                                 const float* __restrict__ w_out) {
    extern __shared__ float cs[];
    float* A   = cs;          // [6*32*32]
    float* Wsh = cs + 6144;   // [32*192]
    __shared__ float sinvsh[C_];
    int oc = blockIdx.x, b = blockIdx.y;
    int o0 = oc * 32;
    int tid = threadIdx.x;

    if (tid < C_) {
        float sk = g_ssk[b * C_ + tid] + g_ssk[B_ * C_ + b * C_ + tid];
        sinvsh[tid] = 1.f / fmaxf(sqrtf(sk), 1e-12f);
    }
    for (int i = tid; i < 32 * 192; i += 256) {
        int o = i / 192, c = i - o * 192;
        Wsh[i] = w_out[(o0 + o) * C_ + c];
    }
    __syncthreads();
    if (tid < C_) {
        int h = tid >> 5, cl = tid & 31;
        float sq = g_ssq[b * C_ + tid] + g_ssq[B_ * C_ + b * C_ + tid];
        float nq = fmaxf(sqrtf(sq), 1e-12f);
        float sc = temp[h] / nq;
        const float* Gr = g_G + ((b * NH_ + h) << 10) + cl * HD_;
        const float* si = sinvsh + h * HD_;
        float row[32], mx = -3.4e38f;
#pragma unroll
        for (int d = 0; d < 32; d++) {
            float v = Gr[d] * sc * si[d];
            row[d] = v;
            mx = fmaxf(mx, v);
        }
        float s = 0.f;
#pragma unroll
        for (int d = 0; d < 32; d++) { row[d] = expf(row[d] - mx); s += row[d]; }
        float inv = 1.f / s;
#pragma unroll
        for (int d = 0; d < 32; d++) A[h * 1024 + cl * 32 + d] = row[d] * inv;
    }
    __syncthreads();
    float* Mb = g_M + (size_t)b * C_ * C_ + (size_t)o0 * C_;
    for (int i = tid; i < 32 * 192; i += 256) {
        int o = i / 192, g = i - o * 192;
        int h = g >> 5, d = g & 31;
        const float* wr = Wsh + o * 192 + h * 32;
        const float* Ar = A + h * 1024 + d;
        float acc = 0.f;
#pragma unroll
        for (int cl = 0; cl < 32; cl++) acc = fmaf(wr[cl], Ar[cl * 32], acc);
        Mb[i] = acc;
    }
}

// ---------------------------------------------------------------------------
// K4: out[b] = M[b](192x192) @ v[b](192xN) + b_out via mma.sync fp16.
// 6 warps x 32 rows (two m16 tiles per warp), n-tile 512, 8 stages of 64,
// 2 CTAs/SM (grid 256). (unchanged from round 16)
// ---------------------------------------------------------------------------
#define KSTRB 144                 // bytes per k-row (64 halves + 8 pad)
#define BTILEB (192 * KSTRB)      // bytes per buffer = 27648
#define GEMM_SMEM (2 * BTILEB)    // 55296

__global__ __launch_bounds__(192, 2) void gemm_out_k(const float* __restrict__ b_out,
                                                     float* __restrict__ out) {
    extern __shared__ char Bsm[];
    unsigned sbase = su32(Bsm);
    int tid = threadIdx.x, wid = tid >> 5, lid = tid & 31;
    int b = blockIdx.y;
    int n0 = blockIdx.x * 512;

    const float* Mg = g_M + (size_t)b * C_ * C_;
    const __half* vb = g_v + (size_t)b * C_ * N_ + n0;

    int g = lid >> 2, t = lid & 3;
    int rr[2];
    rr[0] = 32 * wid + g;
    rr[1] = 32 * wid + 16 + g;
    unsigned ah[2][12][4];
#pragma unroll
    for (int m = 0; m < 2; m++)
#pragma unroll
        for (int j = 0; j < 12; j++) {
            const float* m0 = Mg + (size_t)rr[m] * C_ + 16 * j + 2 * t;
            const float* m1 = Mg + (size_t)(rr[m] + 8) * C_ + 16 * j + 2 * t;
            __half2 p0 = __floats2half2_rn(m0[0], m0[1]);
            __half2 p1 = __floats2half2_rn(m1[0], m1[1]);
            __half2 p2 = __floats2half2_rn(m0[8], m0[9]);
            __half2 p3 = __floats2half2_rn(m1[8], m1[9]);
            ah[m][j][0] = *(unsigned*)&p0;
            ah[m][j][1] = *(unsigned*)&p1;
            ah[m][j][2] = *(unsigned*)&p2;
            ah[m][j][3] = *(unsigned*)&p3;
        }
    float bias[2][2];
#pragma unroll
    for (int m = 0; m < 2; m++) {
        bias[m][0] = b_out[rr[m]];
        bias[m][1] = b_out[rr[m] + 8];
    }

    auto stageB = [&](int s, int buf) {
        unsigned dbase = sbase + (unsigned)buf * BTILEB;
#pragma unroll
        for (int i = 0; i < 8; i++) {
            int e = tid + i * 192;
            int kk = e >> 3, c8 = (e & 7) * 8;
            CP_ASYNC16(dbase + kk * KSTRB + (e & 7) * 16,
                       vb + (size_t)kk * N_ + s * 64 + c8);
        }
        CP_COMMIT();
    };

    stageB(0, 0);

    for (int s = 0; s < 8; s++) {
        int buf = s & 1;
        if (s < 7) { stageB(s + 1, buf ^ 1); CP_WAIT(1); }
        else       { CP_WAIT(0); }
        __syncthreads();
        unsigned bbase = sbase + (unsigned)buf * BTILEB;
        unsigned lrow = (lid & 15);
        unsigned lcolsel = (lid >> 4);
#pragma unroll
        for (int np = 0; np < 4; np++) {
            float ca[2][4], cb[2][4];
#pragma unroll
            for (int m = 0; m < 2; m++) {
                ca[m][0] = bias[m][0]; ca[m][1] = bias[m][0];
                ca[m][2] = bias[m][1]; ca[m][3] = bias[m][1];
                cb[m][0] = bias[m][0]; cb[m][1] = bias[m][0];
                cb[m][2] = bias[m][1]; cb[m][3] = bias[m][1];
            }
            unsigned coladdr = bbase + 16 * (2 * np + lcolsel);
#pragma unroll
            for (int j = 0; j < 12; j++) {
                unsigned b0, b1, b2, b3;
                ldsm_x4_t(b0, b1, b2, b3, coladdr + (16 * j + lrow) * KSTRB);
#pragma unroll
                for (int m = 0; m < 2; m++) {
                    mma_fp16(ca[m][0], ca[m][1], ca[m][2], ca[m][3],
                             ah[m][j][0], ah[m][j][1], ah[m][j][2], ah[m][j][3], b0, b1);
                    mma_fp16(cb[m][0], cb[m][1], cb[m][2], cb[m][3],
                             ah[m][j][0], ah[m][j][1], ah[m][j][2], ah[m][j][3], b2, b3);
                }
            }
            int col = n0 + s * 64 + 16 * np + 2 * t;
#pragma unroll
            for (int m = 0; m < 2; m++) {
                float* op0 = out + (size_t)(b * C_ + rr[m]) * N_ + col;
                float* op1 = out + (size_t)(b * C_ + rr[m] + 8) * N_ + col;
                *(float2*)op0       = make_float2(ca[m][0], ca[m][1]);
                *(float2*)op1       = make_float2(ca[m][2], ca[m][3]);
                *(float2*)(op0 + 8) = make_float2(cb[m][0], cb[m][1]);
                *(float2*)(op1 + 8) = make_float2(cb[m][2], cb[m][3]);
            }
        }
        __syncthreads();
    }
}

// ---------------------------------------------------------------------------
extern "C" void kernel_launch(void* const* d_in, const int* in_sizes, int n_in,
                              void* d_out, int out_size) {
    const float* x     = (const float*)d_in[0];
    const float* w_qkv = (const float*)d_in[1];
    const float* b_qkv = (const float*)d_in[2];
    const float* temp  = (const float*)d_in[3];
    const float* w_out = (const float*)d_in[4];
    const float* b_out = (const float*)d_in[5];
    float* out = (float*)d_out;

    (void)in_sizes; (void)n_in; (void)out_size;

    static int inited = 0;
    const int conv_smem = 66 * 132 * 4;
    const int comp_smem = (6144 + 32 * 192) * 4;
    if (!inited) {
        cudaFuncSetAttribute(conv_k,     cudaFuncAttributeMaxDynamicSharedMemorySize, conv_smem);
        cudaFuncSetAttribute(gram_k,     cudaFuncAttributeMaxDynamicSharedMemorySize, GRAM_SMEM);
        cudaFuncSetAttribute(compose_k,  cudaFuncAttributeMaxDynamicSharedMemorySize, comp_smem);
        cudaFuncSetAttribute(gemm_out_k, cudaFuncAttributeMaxDynamicSharedMemorySize, GEMM_SMEM);
        inited = 1;
    }

    // 7 launches; profiled launch (idx 3) = conv_k (verify f32x2 conv).
    nop_k<<<1, 32>>>();
    nop_k<<<1, 32>>>();
    nop_k<<<1, 32>>>();
    conv_k<<<dim3(C_, 2, B_), 256, conv_smem>>>(x, w_qkv, b_qkv);
    gram_k<<<dim3(16, NH_, B_), 128, GRAM_SMEM>>>();
    compose_k<<<dim3(6, B_), 256, comp_smem>>>(temp, w_out);
    gemm_out_k<<<dim3(N_ / 512, B_), 192, GEMM_SMEM>>>(b_out, out);
}